// round 12
// baseline (speedup 1.0000x reference)
#include <cuda_runtime.h>
#include <cstdint>

// ---------------------------------------------------------------------------
// SuperpointGenerator v4:
//  - counts packed 2x16-bit per u32 (native atomicAdd; counts <= ~60)
//  - count-CDF ge[c] AND per-chunk occupancy built from atomicAdd transition
//    values inside k_count (no separate occupancy pass)
//  - scanB fused with threshold selection (one per-batch block)
//  - scanC assigns gids + labels int16 in-place + emits top-512 candidates
//  - bitonic rank of candidates; final gather vectorized 4 pts/thread
//  Output float32 labels.
// ---------------------------------------------------------------------------

#define BN     16
#define NP     500000
#define TOT    (BN * NP)          // 8,000,000
#define HS     1228800            // halfword slots per batch (|vid| <= 614399)
#define HOFF   614400
#define HTOT   (BN * HS)
#define NW     (HTOT / 2)         // u32 words
#define NCHUNK 300
#define CHUNK  4096               // halfwords per chunk
#define MAXSP  512
#define CMAX   256
#define KCAP   4096
#define PBLK4  489                // ceil(NP / 1024): 4 pts/thread, 256 thr

__device__ unsigned int d_cnt32[NW];          // 2x16b counts, then int16 labels
__device__ int  d_slots[TOT];                 // per-point halfword slot
__device__ int  d_ge[BN * CMAX];              // ge[c] = #voxels count >= c
__device__ int  d_part[BN * NCHUNK];          // per-chunk occupancy sums
__device__ int  d_choff[BN * NCHUNK];         // exclusive chunk offsets
__device__ int  d_T[BN];                      // threshold count
__device__ int  d_U[BN];                      // unique voxels
__device__ int  d_K[BN];                      // candidate counts
__device__ unsigned long long d_cand[BN * KCAP];

// --- init --------------------------------------------------------------------
__global__ void k_init() {
    int i = blockIdx.x * blockDim.x + threadIdx.x;   // grid = NW/4
    if (i < NW / 4) ((int4*)d_cnt32)[i] = make_int4(0, 0, 0, 0);
    if (i < BN * CMAX) d_ge[i] = 0;
    if (i < BN * NCHUNK) d_part[i] = 0;
    if (i < BN) d_K[i] = 0;
}

// --- count: 4 pts/thread, packed atomics, CDF + chunk occupancy from trans ---
__global__ void k_count(const float* __restrict__ coords) {
    __shared__ int hist[CMAX];
    for (int c = threadIdx.x; c < CMAX; c += 256) hist[c] = 0;
    __syncthreads();
    int p0 = blockIdx.x * 1024 + threadIdx.x * 4;
    int b = blockIdx.y;
    if (p0 < NP) {                      // NP % 4 == 0: whole quad valid
        size_t base = ((size_t)b * NP + p0) * 3;
        const float4* cp = (const float4*)(coords + base);   // 16B aligned
        float4 v0 = cp[0], v1 = cp[1], v2 = cp[2];
        float px[4] = {v0.x, v0.w, v1.z, v2.y};
        float py[4] = {v0.y, v1.x, v1.w, v2.z};
        float pz[4] = {v0.z, v1.y, v2.x, v2.w};
        int4 sl;
        int* slp = &sl.x;
#pragma unroll
        for (int q = 0; q < 4; q++) {
            // match jax: f32 divide (div.rn), truncate toward zero
            int x = (int)(px[q] / 0.2f);
            int y = (int)(py[q] / 0.2f);
            int z = (int)(pz[q] / 0.2f);
            int slot = x * 10000 + y * 100 + z + HOFF;
            slot = min(max(slot, 0), HS - 1);
            slp[q] = slot;
            int idx = b * HS + slot;
            int sh16 = (idx & 1) * 16;
            unsigned old = atomicAdd(&d_cnt32[idx >> 1], 1u << sh16);
            int t = (int)((old >> sh16) & 0xFFFFu) + 1;    // raised count to t
            atomicAdd(&hist[min(t, CMAX - 1)], 1);
            if (t == 1)                                    // new unique voxel
                atomicAdd(&d_part[b * NCHUNK + (slot >> 12)], 1);
        }
        *(int4*)&d_slots[(size_t)b * NP + p0] = sl;
    }
    __syncthreads();
    for (int c = threadIdx.x; c < CMAX; c += 256) {
        int h = hist[c];
        if (h) atomicAdd(&d_ge[b * CMAX + c], h);          // ge[c]: #voxels >= c
    }
}

// --- scanB + threshold: one block per batch ----------------------------------
__global__ void k_scanB() {
    __shared__ int sh[512];
    __shared__ int mx[256];
    int b = blockIdx.x;
    int t = threadIdx.x;
    // threshold: largest c with ge[c] >= 512
    if (t < CMAX) {
        int cand = 1;
        if (t >= 1 && d_ge[b * CMAX + t] >= MAXSP) cand = t;
        mx[t] = cand;
    }
    // chunk-offset scan
    int v = (t < NCHUNK) ? d_part[b * NCHUNK + t] : 0;
    sh[t] = v;
    __syncthreads();
    for (int off = 1; off < 512; off <<= 1) {
        int u = (t >= off) ? sh[t - off] : 0;
        __syncthreads();
        sh[t] += u;
        __syncthreads();
    }
    if (t < NCHUNK) d_choff[b * NCHUNK + t] = sh[t] - v;   // exclusive
    // reduce threshold max
    for (int off = 128; off > 0; off >>= 1) {
        if (t < off && t + off < CMAX) mx[t] = max(mx[t], mx[t + off]);
        __syncthreads();
    }
    if (t == 0) {
        d_T[b] = mx[0];
        d_U[b] = d_ge[b * CMAX + 1];
    }
}

// --- scanC: gid assign, labels in-place (int16), candidates ------------------
__global__ void k_scanC() {
    __shared__ int sh[256];
    int blk = blockIdx.x;
    int b  = blk / NCHUNK;
    int cx = blk % NCHUNK;
    int t  = threadIdx.x;
    int wbase = blk * (CHUNK / 2) + t * 8;     // 16 halfwords per thread
    unsigned w[8];
    {
        const uint4* p = (const uint4*)&d_cnt32[wbase];
        uint4 v0 = p[0], v1 = p[1];
        w[0] = v0.x; w[1] = v0.y; w[2] = v0.z; w[3] = v0.w;
        w[4] = v1.x; w[5] = v1.y; w[6] = v1.z; w[7] = v1.w;
    }
    int cv[16];
    int mysum = 0;
#pragma unroll
    for (int j = 0; j < 8; j++) {
        cv[2 * j]     = (int)(w[j] & 0xFFFFu);
        cv[2 * j + 1] = (int)(w[j] >> 16);
        mysum += (cv[2 * j] != 0) + (cv[2 * j + 1] != 0);
    }
    sh[t] = mysum;
    __syncthreads();
    for (int off = 1; off < 256; off <<= 1) {
        int u = (t >= off) ? sh[t - off] : 0;
        __syncthreads();
        sh[t] += u;
        __syncthreads();
    }
    int g = d_choff[blk] + sh[t] - mysum;
    int T = d_T[b];
    bool big = (d_U[b] > MAXSP);
#pragma unroll
    for (int j = 0; j < 16; j++) {
        int c = cv[j];
        int lab = 0;
        if (c) {
            lab = big ? -1 : g;
            if (big && c >= T) {
                int slot = cx * CHUNK + t * 16 + j;    // slot within batch
                int k = atomicAdd(&d_K[b], 1);
                if (k < KCAP) {
                    unsigned long long key =
                        ((unsigned long long)(255 - min(c, 255)) << 40) |
                        ((unsigned long long)(unsigned)g << 21) |
                        (unsigned)slot;
                    d_cand[b * KCAP + k] = key;
                }
            }
            g++;
        }
        if (j & 1) w[j >> 1] = (w[j >> 1] & 0x0000FFFFu) | ((unsigned)(lab & 0xFFFF) << 16);
        else       w[j >> 1] = (w[j >> 1] & 0xFFFF0000u) | (unsigned)(lab & 0xFFFF);
    }
    {
        uint4* p = (uint4*)&d_cnt32[wbase];
        p[0] = make_uint4(w[0], w[1], w[2], w[3]);
        p[1] = make_uint4(w[4], w[5], w[6], w[7]);
    }
}

// --- rank: bitonic sort candidates, write winner labels (int16) --------------
__global__ void k_rank() {
    __shared__ unsigned long long sk[KCAP];     // 32 KB
    int b = blockIdx.x;
    if (d_U[b] <= MAXSP) return;
    int K = min(d_K[b], KCAP);
    int t = threadIdx.x;
    for (int i = t; i < KCAP; i += 1024)
        sk[i] = (i < K) ? d_cand[b * KCAP + i] : ~0ULL;
    __syncthreads();
    for (int size = 2; size <= KCAP; size <<= 1) {
        for (int stride = size >> 1; stride > 0; stride >>= 1) {
            for (int i = t; i < KCAP; i += 1024) {
                int j = i ^ stride;
                if (j > i) {
                    unsigned long long a = sk[i], bb = sk[j];
                    bool up = ((i & size) == 0);
                    if ((a > bb) == up) { sk[i] = bb; sk[j] = a; }
                }
            }
            __syncthreads();
        }
    }
    unsigned short* ph = (unsigned short*)d_cnt32;
    for (int i = t; i < MAXSP; i += 1024) {
        if (i < K) {
            int slot = (int)(sk[i] & 0x1FFFFFu);
            ph[b * HS + slot] = (unsigned short)i;
        }
    }
}

// --- final: 4 pts/thread gather int16 labels, emit float32 -------------------
__global__ void k_final(float* __restrict__ out) {
    int i0 = (blockIdx.x * 256 + threadIdx.x) * 4;
    if (i0 >= TOT) return;                      // TOT % 4 == 0
    int b = i0 / NP;                            // quad never straddles batches
    int4 sl = *(const int4*)&d_slots[i0];
    const short* ph = (const short*)d_cnt32 + (size_t)b * HS;
    float4 o;
    o.x = (float)ph[sl.x];
    o.y = (float)ph[sl.y];
    o.z = (float)ph[sl.z];
    o.w = (float)ph[sl.w];
    *(float4*)&out[i0] = o;
}

extern "C" void kernel_launch(void* const* d_in, const int* in_sizes, int n_in,
                              void* d_out, int out_size) {
    const float* coords = (const float*)d_in[0];
    float* out = (float*)d_out;
    cudaStream_t s = 0;

    k_init <<<(NW / 4 + 255) / 256, 256, 0, s>>>();
    k_count<<<dim3(PBLK4, BN), 256, 0, s>>>(coords);
    k_scanB<<<BN, 512, 0, s>>>();
    k_scanC<<<BN * NCHUNK, 256, 0, s>>>();
    k_rank <<<BN, 1024, 0, s>>>();
    k_final<<<(TOT / 4 + 255) / 256, 256, 0, s>>>(out);
}

// round 14
// speedup vs baseline: 1.4462x; 1.4462x over previous
#include <cuda_runtime.h>
#include <cstdint>

// ---------------------------------------------------------------------------
// SuperpointGenerator v5 (v3 core + safe v4 fusions):
//  - counts packed 2x16-bit per u32 (native atomicAdd)
//  - count-CDF ge[c] from atomicAdd transition values inside k_count
//  - occupancy via scanA (proven 12us) ; scanB fused with threshold
//  - scanC: shuffle-scan (2 syncs), gid assign, int16 labels in-place,
//    top-512 candidates ; bitonic rank ; vectorized final gather
//  Output float32 labels.
// ---------------------------------------------------------------------------

#define BN     16
#define NP     500000
#define TOT    (BN * NP)
#define HS     1228800            // halfword slots per batch (|vid| <= 614399)
#define HOFF   614400
#define HTOT   (BN * HS)
#define NW     (HTOT / 2)         // u32 words
#define NCHUNK 300
#define CHUNK  4096               // halfwords per chunk
#define MAXSP  512
#define CMAX   256
#define KCAP   4096
#define PBLK   1954               // ceil(NP/256)

__device__ unsigned int d_cnt32[NW];          // 2x16b counts, then int16 labels
__device__ int  d_slots[TOT];                 // per-point halfword slot
__device__ int  d_ge[BN * CMAX];              // ge[c] = #voxels count >= c
__device__ int  d_part[BN * NCHUNK];          // per-chunk occupancy sums
__device__ int  d_choff[BN * NCHUNK];         // exclusive chunk offsets
__device__ int  d_T[BN];                      // threshold count
__device__ int  d_U[BN];                      // unique voxels
__device__ int  d_K[BN];                      // candidate counts
__device__ unsigned long long d_cand[BN * KCAP];

// --- init --------------------------------------------------------------------
__global__ void k_init() {
    int i = blockIdx.x * blockDim.x + threadIdx.x;   // grid = NW/4
    if (i < NW / 4) ((int4*)d_cnt32)[i] = make_int4(0, 0, 0, 0);
    if (i < BN * CMAX) d_ge[i] = 0;
    if (i < BN) d_K[i] = 0;
}

// --- count: 1 pt/thread (proven), packed atomic + transition CDF -------------
__global__ void k_count(const float* __restrict__ coords) {
    __shared__ int hist[CMAX];
    for (int c = threadIdx.x; c < CMAX; c += 256) hist[c] = 0;
    __syncthreads();
    int p = blockIdx.x * 256 + threadIdx.x;
    int b = blockIdx.y;
    if (p < NP) {
        size_t i = (size_t)b * NP + p;
        const float* c = coords + i * 3;
        // match jax: f32 divide (div.rn), truncate toward zero
        int x = (int)(c[0] / 0.2f);
        int y = (int)(c[1] / 0.2f);
        int z = (int)(c[2] / 0.2f);
        int slot = x * 10000 + y * 100 + z + HOFF;
        slot = min(max(slot, 0), HS - 1);
        d_slots[i] = slot;
        int idx = b * HS + slot;
        int sh16 = (idx & 1) * 16;
        unsigned old = atomicAdd(&d_cnt32[idx >> 1], 1u << sh16);
        int t = (int)((old >> sh16) & 0xFFFFu) + 1;   // raised count to t
        atomicAdd(&hist[min(t, CMAX - 1)], 1);
    }
    __syncthreads();
    for (int c = threadIdx.x; c < CMAX; c += 256) {
        int h = hist[c];
        if (h) atomicAdd(&d_ge[b * CMAX + c], h);     // ge[c]: #voxels >= c
    }
}

// --- scanA: per-chunk occupancy (nonzero halfwords) --------------------------
__global__ void k_scanA() {
    __shared__ int occ[256];
    int blk = blockIdx.x;
    int wbase = blk * (CHUNK / 2) + threadIdx.x * 8;
    const uint4* p = (const uint4*)&d_cnt32[wbase];
    uint4 v0 = p[0], v1 = p[1];
    unsigned w[8] = {v0.x, v0.y, v0.z, v0.w, v1.x, v1.y, v1.z, v1.w};
    int s = 0;
#pragma unroll
    for (int j = 0; j < 8; j++)
        s += ((w[j] & 0xFFFFu) != 0) + ((w[j] >> 16) != 0);
    occ[threadIdx.x] = s;
    __syncthreads();
    for (int off = 128; off > 0; off >>= 1) {
        if (threadIdx.x < off) occ[threadIdx.x] += occ[threadIdx.x + off];
        __syncthreads();
    }
    if (threadIdx.x == 0) d_part[blk] = occ[0];
}

// --- scanB + threshold: one block per batch ----------------------------------
__global__ void k_scanB() {
    __shared__ int sh[512];
    __shared__ int mx[256];
    int b = blockIdx.x;
    int t = threadIdx.x;
    if (t < CMAX) {
        int cand = 1;
        if (t >= 1 && d_ge[b * CMAX + t] >= MAXSP) cand = t;
        mx[t] = cand;
    }
    int v = (t < NCHUNK) ? d_part[b * NCHUNK + t] : 0;
    sh[t] = v;
    __syncthreads();
    for (int off = 1; off < 512; off <<= 1) {
        int u = (t >= off) ? sh[t - off] : 0;
        __syncthreads();
        sh[t] += u;
        __syncthreads();
    }
    if (t < NCHUNK) d_choff[b * NCHUNK + t] = sh[t] - v;   // exclusive
    for (int off = 128; off > 0; off >>= 1) {
        if (t < off && t + off < CMAX) mx[t] = max(mx[t], mx[t + off]);
        __syncthreads();
    }
    if (t == 0) {
        d_T[b] = mx[0];                 // largest c with ge[c] >= 512
        d_U[b] = d_ge[b * CMAX + 1];
    }
}

// --- scanC: shuffle-scan gid assign, labels in-place, candidates -------------
__global__ void k_scanC() {
    __shared__ int warpincl[8];
    int blk = blockIdx.x;
    int b  = blk / NCHUNK;
    int cx = blk % NCHUNK;
    int t  = threadIdx.x;
    int lane = t & 31, wrp = t >> 5;
    int wbase = blk * (CHUNK / 2) + t * 8;     // 16 halfwords per thread
    unsigned w[8];
    {
        const uint4* p = (const uint4*)&d_cnt32[wbase];
        uint4 v0 = p[0], v1 = p[1];
        w[0] = v0.x; w[1] = v0.y; w[2] = v0.z; w[3] = v0.w;
        w[4] = v1.x; w[5] = v1.y; w[6] = v1.z; w[7] = v1.w;
    }
    int cv[16];
    int mysum = 0;
#pragma unroll
    for (int j = 0; j < 8; j++) {
        cv[2 * j]     = (int)(w[j] & 0xFFFFu);
        cv[2 * j + 1] = (int)(w[j] >> 16);
        mysum += (cv[2 * j] != 0) + (cv[2 * j + 1] != 0);
    }
    // warp inclusive scan
    int inc = mysum;
#pragma unroll
    for (int o = 1; o < 32; o <<= 1) {
        int u = __shfl_up_sync(0xFFFFFFFFu, inc, o);
        if (lane >= o) inc += u;
    }
    if (lane == 31) warpincl[wrp] = inc;
    __syncthreads();
    int woff = 0;
    if (wrp > 0) {
#pragma unroll
        for (int ww = 0; ww < 7; ww++)
            if (ww < wrp) woff += warpincl[ww];
    }
    int g = d_choff[blk] + woff + inc - mysum;
    int T = d_T[b];
    bool big = (d_U[b] > MAXSP);
#pragma unroll
    for (int j = 0; j < 16; j++) {
        int c = cv[j];
        int lab = 0;
        if (c) {
            lab = big ? -1 : g;
            if (big && c >= T) {
                int slot = cx * CHUNK + t * 16 + j;    // slot within batch
                int k = atomicAdd(&d_K[b], 1);
                if (k < KCAP) {
                    unsigned long long key =
                        ((unsigned long long)(255 - min(c, 255)) << 40) |
                        ((unsigned long long)(unsigned)g << 21) |
                        (unsigned)slot;
                    d_cand[b * KCAP + k] = key;
                }
            }
            g++;
        }
        if (j & 1) w[j >> 1] = (w[j >> 1] & 0x0000FFFFu) | ((unsigned)(lab & 0xFFFF) << 16);
        else       w[j >> 1] = (w[j >> 1] & 0xFFFF0000u) | (unsigned)(lab & 0xFFFF);
    }
    {
        uint4* p = (uint4*)&d_cnt32[wbase];
        p[0] = make_uint4(w[0], w[1], w[2], w[3]);
        p[1] = make_uint4(w[4], w[5], w[6], w[7]);
    }
}

// --- rank: bitonic sort candidates, write winner labels (int16) --------------
__global__ void k_rank() {
    __shared__ unsigned long long sk[KCAP];     // 32 KB
    int b = blockIdx.x;
    if (d_U[b] <= MAXSP) return;
    int K = min(d_K[b], KCAP);
    int t = threadIdx.x;
    for (int i = t; i < KCAP; i += 1024)
        sk[i] = (i < K) ? d_cand[b * KCAP + i] : ~0ULL;
    __syncthreads();
    for (int size = 2; size <= KCAP; size <<= 1) {
        for (int stride = size >> 1; stride > 0; stride >>= 1) {
            for (int i = t; i < KCAP; i += 1024) {
                int j = i ^ stride;
                if (j > i) {
                    unsigned long long a = sk[i], bb = sk[j];
                    bool up = ((i & size) == 0);
                    if ((a > bb) == up) { sk[i] = bb; sk[j] = a; }
                }
            }
            __syncthreads();
        }
    }
    unsigned short* ph = (unsigned short*)d_cnt32;
    for (int i = t; i < MAXSP; i += 1024) {
        if (i < K) {
            int slot = (int)(sk[i] & 0x1FFFFFu);
            ph[b * HS + slot] = (unsigned short)i;
        }
    }
}

// --- final: 4 pts/thread gather int16 labels, emit float32 -------------------
__global__ void k_final(float* __restrict__ out) {
    int i0 = (blockIdx.x * 256 + threadIdx.x) * 4;
    if (i0 >= TOT) return;                      // TOT % 4 == 0
    int b = i0 / NP;                            // quad never straddles batches
    int4 sl = *(const int4*)&d_slots[i0];
    const short* ph = (const short*)d_cnt32 + (size_t)b * HS;
    float4 o;
    o.x = (float)ph[sl.x];
    o.y = (float)ph[sl.y];
    o.z = (float)ph[sl.z];
    o.w = (float)ph[sl.w];
    *(float4*)&out[i0] = o;
}

extern "C" void kernel_launch(void* const* d_in, const int* in_sizes, int n_in,
                              void* d_out, int out_size) {
    const float* coords = (const float*)d_in[0];
    float* out = (float*)d_out;
    cudaStream_t s = 0;

    k_init <<<(NW / 4 + 255) / 256, 256, 0, s>>>();
    k_count<<<dim3(PBLK, BN), 256, 0, s>>>(coords);
    k_scanA<<<BN * NCHUNK, 256, 0, s>>>();
    k_scanB<<<BN, 512, 0, s>>>();
    k_scanC<<<BN * NCHUNK, 256, 0, s>>>();
    k_rank <<<BN, 1024, 0, s>>>();
    k_final<<<(TOT / 4 + 255) / 256, 256, 0, s>>>(out);
}

// round 15
// speedup vs baseline: 1.7416x; 1.2043x over previous
#include <cuda_runtime.h>
#include <cstdint>

// ---------------------------------------------------------------------------
// SuperpointGenerator v6:
//  - k_count: pure streaming (coords -> slot store -> fire-and-forget RED.ADD
//    on packed 2x16-bit counts). No atomic-return dependency, no smem hist.
//  - k_scanA: occupancy + exact-count histogram (~250 smem atomics/block,
//    final values) -> d_hc
//  - k_scanB: reverse-scan hc -> ge CDF, threshold T, U, chunk offsets
//  - scanC: shuffle-scan gid assign, int16 labels in-place, candidates
//  - bitonic rank ; vectorized final gather. Output float32 labels.
// ---------------------------------------------------------------------------

#define BN     16
#define NP     500000
#define TOT    (BN * NP)
#define HS     1228800            // halfword slots per batch (|vid| <= 614399)
#define HOFF   614400
#define HTOT   (BN * HS)
#define NW     (HTOT / 2)         // u32 words
#define NCHUNK 300
#define CHUNK  4096               // halfwords per chunk
#define MAXSP  512
#define CMAX   256
#define KCAP   4096
#define PBLK   1954               // ceil(NP/256)

__device__ unsigned int d_cnt32[NW];          // 2x16b counts, then int16 labels
__device__ int  d_slots[TOT];                 // per-point halfword slot
__device__ int  d_hc[BN * CMAX];              // hc[c] = #voxels with count == c
__device__ int  d_part[BN * NCHUNK];          // per-chunk occupancy sums
__device__ int  d_choff[BN * NCHUNK];         // exclusive chunk offsets
__device__ int  d_T[BN];                      // threshold count
__device__ int  d_U[BN];                      // unique voxels
__device__ int  d_K[BN];                      // candidate counts
__device__ unsigned long long d_cand[BN * KCAP];

// --- init --------------------------------------------------------------------
__global__ void k_init() {
    int i = blockIdx.x * blockDim.x + threadIdx.x;   // grid = NW/4
    if (i < NW / 4) ((int4*)d_cnt32)[i] = make_int4(0, 0, 0, 0);
    if (i < BN * CMAX) d_hc[i] = 0;
    if (i < BN) d_K[i] = 0;
}

// --- count: pure streaming, unreturned RED on packed counts ------------------
__global__ void k_count(const float* __restrict__ coords) {
    int p = blockIdx.x * 256 + threadIdx.x;
    int b = blockIdx.y;
    if (p >= NP) return;
    size_t i = (size_t)b * NP + p;
    const float* c = coords + i * 3;
    // match jax: f32 divide (div.rn), truncate toward zero
    int x = (int)(c[0] / 0.2f);
    int y = (int)(c[1] / 0.2f);
    int z = (int)(c[2] / 0.2f);
    int slot = x * 10000 + y * 100 + z + HOFF;
    slot = min(max(slot, 0), HS - 1);
    d_slots[i] = slot;
    int idx = b * HS + slot;
    atomicAdd(&d_cnt32[idx >> 1], 1u << ((idx & 1) * 16));   // result unused: RED
}

// --- scanA: per-chunk occupancy + exact-count histogram ----------------------
__global__ void k_scanA() {
    __shared__ int occ[256];
    __shared__ int hist[CMAX];
    for (int c = threadIdx.x; c < CMAX; c += 256) hist[c] = 0;
    __syncthreads();
    int blk = blockIdx.x;
    int b = blk / NCHUNK;
    int wbase = blk * (CHUNK / 2) + threadIdx.x * 8;
    const uint4* p = (const uint4*)&d_cnt32[wbase];
    uint4 v0 = p[0], v1 = p[1];
    unsigned w[8] = {v0.x, v0.y, v0.z, v0.w, v1.x, v1.y, v1.z, v1.w};
    int s = 0;
#pragma unroll
    for (int j = 0; j < 8; j++) {
        int c0 = (int)(w[j] & 0xFFFFu);
        int c1 = (int)(w[j] >> 16);
        if (c0) { s++; atomicAdd(&hist[min(c0, CMAX - 1)], 1); }
        if (c1) { s++; atomicAdd(&hist[min(c1, CMAX - 1)], 1); }
    }
    occ[threadIdx.x] = s;
    __syncthreads();
    for (int off = 128; off > 0; off >>= 1) {
        if (threadIdx.x < off) occ[threadIdx.x] += occ[threadIdx.x + off];
        __syncthreads();
    }
    if (threadIdx.x == 0) d_part[blk] = occ[0];
    for (int c = threadIdx.x; c < CMAX; c += 256) {
        int h = hist[c];
        if (h) atomicAdd(&d_hc[b * CMAX + c], h);
    }
}

// --- scanB: chunk-offset scan + ge CDF (reverse scan of hc) + threshold ------
__global__ void k_scanB() {
    __shared__ int sh[512];
    __shared__ int hs[256];     // hs[i] = sum hc[255-i .. 255] = ge[255-i]
    __shared__ int mx[256];
    int b = blockIdx.x;
    int t = threadIdx.x;
    if (t < CMAX) hs[t] = d_hc[b * CMAX + (CMAX - 1 - t)];
    int v = (t < NCHUNK) ? d_part[b * NCHUNK + t] : 0;
    sh[t] = v;
    __syncthreads();
    for (int off = 1; off < 512; off <<= 1) {
        int u  = (t >= off) ? sh[t - off] : 0;
        int u2 = (t < CMAX && off < CMAX && t >= off) ? hs[t - off] : 0;
        __syncthreads();
        sh[t] += u;
        if (t < CMAX && off < CMAX) hs[t] += u2;
        __syncthreads();
    }
    if (t < NCHUNK) d_choff[b * NCHUNK + t] = sh[t] - v;   // exclusive
    // ge[c] = hs[255 - c]; T = largest c>=1 with ge[c] >= 512
    if (t < CMAX) {
        int cand = 1;
        if (t >= 1 && hs[CMAX - 1 - t] >= MAXSP) cand = t;
        mx[t] = cand;
    }
    __syncthreads();
    for (int off = 128; off > 0; off >>= 1) {
        if (t < off && t + off < CMAX) mx[t] = max(mx[t], mx[t + off]);
        __syncthreads();
    }
    if (t == 0) {
        d_T[b] = mx[0];
        d_U[b] = hs[CMAX - 2];          // ge[1] = total occupied voxels
    }
}

// --- scanC: shuffle-scan gid assign, labels in-place, candidates -------------
__global__ void k_scanC() {
    __shared__ int warpincl[8];
    int blk = blockIdx.x;
    int b  = blk / NCHUNK;
    int cx = blk % NCHUNK;
    int t  = threadIdx.x;
    int lane = t & 31, wrp = t >> 5;
    int wbase = blk * (CHUNK / 2) + t * 8;     // 16 halfwords per thread
    unsigned w[8];
    {
        const uint4* p = (const uint4*)&d_cnt32[wbase];
        uint4 v0 = p[0], v1 = p[1];
        w[0] = v0.x; w[1] = v0.y; w[2] = v0.z; w[3] = v0.w;
        w[4] = v1.x; w[5] = v1.y; w[6] = v1.z; w[7] = v1.w;
    }
    int cv[16];
    int mysum = 0;
#pragma unroll
    for (int j = 0; j < 8; j++) {
        cv[2 * j]     = (int)(w[j] & 0xFFFFu);
        cv[2 * j + 1] = (int)(w[j] >> 16);
        mysum += (cv[2 * j] != 0) + (cv[2 * j + 1] != 0);
    }
    int inc = mysum;
#pragma unroll
    for (int o = 1; o < 32; o <<= 1) {
        int u = __shfl_up_sync(0xFFFFFFFFu, inc, o);
        if (lane >= o) inc += u;
    }
    if (lane == 31) warpincl[wrp] = inc;
    __syncthreads();
    int woff = 0;
#pragma unroll
    for (int ww = 0; ww < 7; ww++)
        if (ww < wrp) woff += warpincl[ww];
    int g = d_choff[blk] + woff + inc - mysum;
    int T = d_T[b];
    bool big = (d_U[b] > MAXSP);
#pragma unroll
    for (int j = 0; j < 16; j++) {
        int c = cv[j];
        int lab = 0;
        if (c) {
            lab = big ? -1 : g;
            if (big && c >= T) {
                int slot = cx * CHUNK + t * 16 + j;    // slot within batch
                int k = atomicAdd(&d_K[b], 1);
                if (k < KCAP) {
                    unsigned long long key =
                        ((unsigned long long)(255 - min(c, 255)) << 40) |
                        ((unsigned long long)(unsigned)g << 21) |
                        (unsigned)slot;
                    d_cand[b * KCAP + k] = key;
                }
            }
            g++;
        }
        if (j & 1) w[j >> 1] = (w[j >> 1] & 0x0000FFFFu) | ((unsigned)(lab & 0xFFFF) << 16);
        else       w[j >> 1] = (w[j >> 1] & 0xFFFF0000u) | (unsigned)(lab & 0xFFFF);
    }
    {
        uint4* p = (uint4*)&d_cnt32[wbase];
        p[0] = make_uint4(w[0], w[1], w[2], w[3]);
        p[1] = make_uint4(w[4], w[5], w[6], w[7]);
    }
}

// --- rank: bitonic sort candidates, write winner labels (int16) --------------
__global__ void k_rank() {
    __shared__ unsigned long long sk[KCAP];     // 32 KB
    int b = blockIdx.x;
    if (d_U[b] <= MAXSP) return;
    int K = min(d_K[b], KCAP);
    int t = threadIdx.x;
    for (int i = t; i < KCAP; i += 1024)
        sk[i] = (i < K) ? d_cand[b * KCAP + i] : ~0ULL;
    __syncthreads();
    for (int size = 2; size <= KCAP; size <<= 1) {
        for (int stride = size >> 1; stride > 0; stride >>= 1) {
            for (int i = t; i < KCAP; i += 1024) {
                int j = i ^ stride;
                if (j > i) {
                    unsigned long long a = sk[i], bb = sk[j];
                    bool up = ((i & size) == 0);
                    if ((a > bb) == up) { sk[i] = bb; sk[j] = a; }
                }
            }
            __syncthreads();
        }
    }
    unsigned short* ph = (unsigned short*)d_cnt32;
    for (int i = t; i < MAXSP; i += 1024) {
        if (i < K) {
            int slot = (int)(sk[i] & 0x1FFFFFu);
            ph[b * HS + slot] = (unsigned short)i;
        }
    }
}

// --- final: 4 pts/thread gather int16 labels, emit float32 -------------------
__global__ void k_final(float* __restrict__ out) {
    int i0 = (blockIdx.x * 256 + threadIdx.x) * 4;
    if (i0 >= TOT) return;                      // TOT % 4 == 0
    int b = i0 / NP;                            // quad never straddles batches
    int4 sl = *(const int4*)&d_slots[i0];
    const short* ph = (const short*)d_cnt32 + (size_t)b * HS;
    float4 o;
    o.x = (float)ph[sl.x];
    o.y = (float)ph[sl.y];
    o.z = (float)ph[sl.z];
    o.w = (float)ph[sl.w];
    *(float4*)&out[i0] = o;
}

extern "C" void kernel_launch(void* const* d_in, const int* in_sizes, int n_in,
                              void* d_out, int out_size) {
    const float* coords = (const float*)d_in[0];
    float* out = (float*)d_out;
    cudaStream_t s = 0;

    k_init <<<(NW / 4 + 255) / 256, 256, 0, s>>>();
    k_count<<<dim3(PBLK, BN), 256, 0, s>>>(coords);
    k_scanA<<<BN * NCHUNK, 256, 0, s>>>();
    k_scanB<<<BN, 512, 0, s>>>();
    k_scanC<<<BN * NCHUNK, 256, 0, s>>>();
    k_rank <<<BN, 1024, 0, s>>>();
    k_final<<<(TOT / 4 + 255) / 256, 256, 0, s>>>(out);
}

// round 17
// speedup vs baseline: 1.7452x; 1.0020x over previous
#include <cuda_runtime.h>
#include <cstdint>

// ---------------------------------------------------------------------------
// SuperpointGenerator v7 (v6 + fast voxelize):
//  - voxelize via x*5.0f with exact div.rn fallback for near-boundary lanes
//    (bitwise-identical result; ~0.02% of lanes take the div path)
//  - k_count: pure streaming, fire-and-forget RED.ADD on packed 2x16b counts
//  - scanA: occupancy + exact-count histogram ; scanB: CDF+threshold+offsets
//  - scanC: shuffle-scan gid assign, int16 labels in-place, candidates
//  - bitonic rank ; vectorized final gather. Output float32 labels.
// ---------------------------------------------------------------------------

#define BN     16
#define NP     500000
#define TOT    (BN * NP)
#define HS     1228800            // halfword slots per batch (|vid| <= 614399)
#define HOFF   614400
#define HTOT   (BN * HS)
#define NW     (HTOT / 2)         // u32 words
#define NCHUNK 300
#define CHUNK  4096               // halfwords per chunk
#define MAXSP  512
#define CMAX   256
#define KCAP   4096
#define PBLK   1954               // ceil(NP/256)

__device__ unsigned int d_cnt32[NW];          // 2x16b counts, then int16 labels
__device__ int  d_slots[TOT];                 // per-point halfword slot
__device__ int  d_hc[BN * CMAX];              // hc[c] = #voxels with count == c
__device__ int  d_part[BN * NCHUNK];          // per-chunk occupancy sums
__device__ int  d_choff[BN * NCHUNK];         // exclusive chunk offsets
__device__ int  d_T[BN];                      // threshold count
__device__ int  d_U[BN];                      // unique voxels
__device__ int  d_K[BN];                      // candidate counts
__device__ unsigned long long d_cand[BN * KCAP];

// voxel index: trunc(x / 0.2f) with div.rn semantics, fast path via *5.0f.
// |x*5 - x/0.2f(exact)| <= ~1.25 ulp; truncations differ only within ~1e-5
// of an integer. Guard band 1e-4 (10x margin), fallback = true division.
__device__ __forceinline__ int vox(float x) {
    float r = x * 5.0f;
    if (fabsf(r - rintf(r)) < 1e-4f) r = x / 0.2f;
    return (int)r;
}

// --- init --------------------------------------------------------------------
__global__ void k_init() {
    int i = blockIdx.x * blockDim.x + threadIdx.x;   // grid covers NW/16
    const int stride = NW / 16;                      // threads total
    int4 z = make_int4(0, 0, 0, 0);
    if (i < stride) {
#pragma unroll
        for (int k = 0; k < 4; k++)
            ((int4*)d_cnt32)[i + k * stride] = z;
    }
    if (i < BN * CMAX) d_hc[i] = 0;
    if (i < BN) d_K[i] = 0;
}

// --- count: pure streaming, unreturned RED on packed counts ------------------
__global__ void k_count(const float* __restrict__ coords) {
    int p = blockIdx.x * 256 + threadIdx.x;
    int b = blockIdx.y;
    if (p >= NP) return;
    size_t i = (size_t)b * NP + p;
    const float* c = coords + i * 3;
    int x = vox(c[0]);
    int y = vox(c[1]);
    int z = vox(c[2]);
    int slot = x * 10000 + y * 100 + z + HOFF;
    slot = min(max(slot, 0), HS - 1);
    d_slots[i] = slot;
    int idx = b * HS + slot;
    atomicAdd(&d_cnt32[idx >> 1], 1u << ((idx & 1) * 16));   // result unused: RED
}

// --- scanA: per-chunk occupancy + exact-count histogram ----------------------
__global__ void k_scanA() {
    __shared__ int occ[256];
    __shared__ int hist[CMAX];
    for (int c = threadIdx.x; c < CMAX; c += 256) hist[c] = 0;
    __syncthreads();
    int blk = blockIdx.x;
    int b = blk / NCHUNK;
    int wbase = blk * (CHUNK / 2) + threadIdx.x * 8;
    const uint4* p = (const uint4*)&d_cnt32[wbase];
    uint4 v0 = p[0], v1 = p[1];
    unsigned w[8] = {v0.x, v0.y, v0.z, v0.w, v1.x, v1.y, v1.z, v1.w};
    int s = 0;
#pragma unroll
    for (int j = 0; j < 8; j++) {
        int c0 = (int)(w[j] & 0xFFFFu);
        int c1 = (int)(w[j] >> 16);
        if (c0) { s++; atomicAdd(&hist[min(c0, CMAX - 1)], 1); }
        if (c1) { s++; atomicAdd(&hist[min(c1, CMAX - 1)], 1); }
    }
    occ[threadIdx.x] = s;
    __syncthreads();
    for (int off = 128; off > 0; off >>= 1) {
        if (threadIdx.x < off) occ[threadIdx.x] += occ[threadIdx.x + off];
        __syncthreads();
    }
    if (threadIdx.x == 0) d_part[blk] = occ[0];
    for (int c = threadIdx.x; c < CMAX; c += 256) {
        int h = hist[c];
        if (h) atomicAdd(&d_hc[b * CMAX + c], h);
    }
}

// --- scanB: chunk-offset scan + ge CDF (reverse scan of hc) + threshold ------
__global__ void k_scanB() {
    __shared__ int sh[512];
    __shared__ int hs[256];     // hs[i] = ge[255-i]
    __shared__ int mx[256];
    int b = blockIdx.x;
    int t = threadIdx.x;
    if (t < CMAX) hs[t] = d_hc[b * CMAX + (CMAX - 1 - t)];
    int v = (t < NCHUNK) ? d_part[b * NCHUNK + t] : 0;
    sh[t] = v;
    __syncthreads();
    for (int off = 1; off < 512; off <<= 1) {
        int u  = (t >= off) ? sh[t - off] : 0;
        int u2 = (t < CMAX && off < CMAX && t >= off) ? hs[t - off] : 0;
        __syncthreads();
        sh[t] += u;
        if (t < CMAX && off < CMAX) hs[t] += u2;
        __syncthreads();
    }
    if (t < NCHUNK) d_choff[b * NCHUNK + t] = sh[t] - v;   // exclusive
    if (t < CMAX) {
        int cand = 1;
        if (t >= 1 && hs[CMAX - 1 - t] >= MAXSP) cand = t;
        mx[t] = cand;
    }
    __syncthreads();
    for (int off = 128; off > 0; off >>= 1) {
        if (t < off && t + off < CMAX) mx[t] = max(mx[t], mx[t + off]);
        __syncthreads();
    }
    if (t == 0) {
        d_T[b] = mx[0];                 // largest c with ge[c] >= 512
        d_U[b] = hs[CMAX - 2];          // ge[1] = occupied voxels
    }
}

// --- scanC: shuffle-scan gid assign, labels in-place, candidates -------------
__global__ void k_scanC() {
    __shared__ int warpincl[8];
    int blk = blockIdx.x;
    int b  = blk / NCHUNK;
    int cx = blk % NCHUNK;
    int t  = threadIdx.x;
    int lane = t & 31, wrp = t >> 5;
    int wbase = blk * (CHUNK / 2) + t * 8;     // 16 halfwords per thread
    unsigned w[8];
    {
        const uint4* p = (const uint4*)&d_cnt32[wbase];
        uint4 v0 = p[0], v1 = p[1];
        w[0] = v0.x; w[1] = v0.y; w[2] = v0.z; w[3] = v0.w;
        w[4] = v1.x; w[5] = v1.y; w[6] = v1.z; w[7] = v1.w;
    }
    int cv[16];
    int mysum = 0;
#pragma unroll
    for (int j = 0; j < 8; j++) {
        cv[2 * j]     = (int)(w[j] & 0xFFFFu);
        cv[2 * j + 1] = (int)(w[j] >> 16);
        mysum += (cv[2 * j] != 0) + (cv[2 * j + 1] != 0);
    }
    int inc = mysum;
#pragma unroll
    for (int o = 1; o < 32; o <<= 1) {
        int u = __shfl_up_sync(0xFFFFFFFFu, inc, o);
        if (lane >= o) inc += u;
    }
    if (lane == 31) warpincl[wrp] = inc;
    __syncthreads();
    int woff = 0;
#pragma unroll
    for (int ww = 0; ww < 7; ww++)
        if (ww < wrp) woff += warpincl[ww];
    int g = d_choff[blk] + woff + inc - mysum;
    int T = d_T[b];
    bool big = (d_U[b] > MAXSP);
#pragma unroll
    for (int j = 0; j < 16; j++) {
        int c = cv[j];
        int lab = 0;
        if (c) {
            lab = big ? -1 : g;
            if (big && c >= T) {
                int slot = cx * CHUNK + t * 16 + j;    // slot within batch
                int k = atomicAdd(&d_K[b], 1);
                if (k < KCAP) {
                    unsigned long long key =
                        ((unsigned long long)(255 - min(c, 255)) << 40) |
                        ((unsigned long long)(unsigned)g << 21) |
                        (unsigned)slot;
                    d_cand[b * KCAP + k] = key;
                }
            }
            g++;
        }
        if (j & 1) w[j >> 1] = (w[j >> 1] & 0x0000FFFFu) | ((unsigned)(lab & 0xFFFF) << 16);
        else       w[j >> 1] = (w[j >> 1] & 0xFFFF0000u) | (unsigned)(lab & 0xFFFF);
    }
    {
        uint4* p = (uint4*)&d_cnt32[wbase];
        p[0] = make_uint4(w[0], w[1], w[2], w[3]);
        p[1] = make_uint4(w[4], w[5], w[6], w[7]);
    }
}

// --- rank: bitonic sort candidates, write winner labels (int16) --------------
__global__ void k_rank() {
    __shared__ unsigned long long sk[KCAP];     // 32 KB
    int b = blockIdx.x;
    if (d_U[b] <= MAXSP) return;
    int K = min(d_K[b], KCAP);
    int t = threadIdx.x;
    for (int i = t; i < KCAP; i += 1024)
        sk[i] = (i < K) ? d_cand[b * KCAP + i] : ~0ULL;
    __syncthreads();
    for (int size = 2; size <= KCAP; size <<= 1) {
        for (int stride = size >> 1; stride > 0; stride >>= 1) {
            for (int i = t; i < KCAP; i += 1024) {
                int j = i ^ stride;
                if (j > i) {
                    unsigned long long a = sk[i], bb = sk[j];
                    bool up = ((i & size) == 0);
                    if ((a > bb) == up) { sk[i] = bb; sk[j] = a; }
                }
            }
            __syncthreads();
        }
    }
    unsigned short* ph = (unsigned short*)d_cnt32;
    for (int i = t; i < MAXSP; i += 1024) {
        if (i < K) {
            int slot = (int)(sk[i] & 0x1FFFFFu);
            ph[b * HS + slot] = (unsigned short)i;
        }
    }
}

// --- final: 4 pts/thread gather int16 labels, emit float32 -------------------
__global__ void k_final(float* __restrict__ out) {
    int i0 = (blockIdx.x * 256 + threadIdx.x) * 4;
    if (i0 >= TOT) return;                      // TOT % 4 == 0
    int b = i0 / NP;                            // quad never straddles batches
    int4 sl = *(const int4*)&d_slots[i0];
    const short* ph = (const short*)d_cnt32 + (size_t)b * HS;
    float4 o;
    o.x = (float)ph[sl.x];
    o.y = (float)ph[sl.y];
    o.z = (float)ph[sl.z];
    o.w = (float)ph[sl.w];
    *(float4*)&out[i0] = o;
}

extern "C" void kernel_launch(void* const* d_in, const int* in_sizes, int n_in,
                              void* d_out, int out_size) {
    const float* coords = (const float*)d_in[0];
    float* out = (float*)d_out;
    cudaStream_t s = 0;

    k_init <<<(NW / 16 + 255) / 256, 256, 0, s>>>();
    k_count<<<dim3(PBLK, BN), 256, 0, s>>>(coords);
    k_scanA<<<BN * NCHUNK, 256, 0, s>>>();
    k_scanB<<<BN, 512, 0, s>>>();
    k_scanC<<<BN * NCHUNK, 256, 0, s>>>();
    k_rank <<<BN, 1024, 0, s>>>();
    k_final<<<(TOT / 4 + 255) / 256, 256, 0, s>>>(out);
}